// round 4
// baseline (speedup 1.0000x reference)
#include <cuda_runtime.h>
#include <cstdint>

// Problem constants
#define B_ 2
#define T_ 2048
#define C_ 1024
#define H_ 16
#define HD_ 64
#define WIN_ 512
#define MAXREL_ 128
#define NBIAS_ 257

// Scratch (device globals; no allocation allowed)
__device__ float g_q[(size_t)B_ * H_ * T_ * HD_];
__device__ float g_k[(size_t)B_ * H_ * T_ * HD_];
__device__ float g_v[(size_t)B_ * H_ * T_ * HD_];
__device__ float g_att[(size_t)B_ * T_ * C_];

// ---------------------------------------------------------------------------
// SGEMM NT: C[m][n] = sum_k A[m][k] * B[n][k]
// BM=BN=128, BK=8, 256 threads, 8x8 per thread.
// MODE 0: C = acc + bias[n]  (plain output)
// MODE 1: scatter into g_q/g_k/g_v with (B,H,T,hd) layout (QKV epilogue)
// ---------------------------------------------------------------------------
template <int MODE>
__global__ __launch_bounds__(256, 2)
void sgemm_nt(const float* __restrict__ A, const float* __restrict__ Bm,
              const float* __restrict__ bias, float* __restrict__ Cout,
              int M, int N, int K) {
    constexpr int BM = 128, BN = 128, BK = 8;
    __shared__ float As[BK][BM];
    __shared__ float Bs[BK][BN];

    const int tid = threadIdx.x;
    const int bm = blockIdx.y * BM;
    const int bn = blockIdx.x * BN;
    const int tr = tid >> 4;   // 0..15
    const int tc = tid & 15;   // 0..15

    const float* Aptr = A + (size_t)bm * K;
    const float* Bptr = Bm + (size_t)bn * K;

    const int lrow = tid >> 1;        // 0..127
    const int lc4 = (tid & 1) << 2;   // 0 or 4

    float acc[8][8];
#pragma unroll
    for (int i = 0; i < 8; i++)
#pragma unroll
        for (int j = 0; j < 8; j++) acc[i][j] = 0.f;

    for (int k0 = 0; k0 < K; k0 += BK) {
        float4 av = *(const float4*)(Aptr + (size_t)lrow * K + k0 + lc4);
        float4 bv = *(const float4*)(Bptr + (size_t)lrow * K + k0 + lc4);
        As[lc4 + 0][lrow] = av.x;
        As[lc4 + 1][lrow] = av.y;
        As[lc4 + 2][lrow] = av.z;
        As[lc4 + 3][lrow] = av.w;
        Bs[lc4 + 0][lrow] = bv.x;
        Bs[lc4 + 1][lrow] = bv.y;
        Bs[lc4 + 2][lrow] = bv.z;
        Bs[lc4 + 3][lrow] = bv.w;
        __syncthreads();
#pragma unroll
        for (int kk = 0; kk < BK; kk++) {
            float4 a0 = *(const float4*)&As[kk][tr * 8];
            float4 a1 = *(const float4*)&As[kk][tr * 8 + 4];
            float4 b0 = *(const float4*)&Bs[kk][tc * 8];
            float4 b1 = *(const float4*)&Bs[kk][tc * 8 + 4];
            float a[8] = {a0.x, a0.y, a0.z, a0.w, a1.x, a1.y, a1.z, a1.w};
            float b[8] = {b0.x, b0.y, b0.z, b0.w, b1.x, b1.y, b1.z, b1.w};
#pragma unroll
            for (int i = 0; i < 8; i++)
#pragma unroll
                for (int j = 0; j < 8; j++) acc[i][j] += a[i] * b[j];
        }
        __syncthreads();
    }

    if (MODE == 0) {
        // plain + bias
#pragma unroll
        for (int i = 0; i < 8; i++) {
            int row = bm + tr * 8 + i;
            float* dst = Cout + (size_t)row * N + bn + tc * 8;
            float4 o0, o1;
            const float* bp = bias + bn + tc * 8;
            o0.x = acc[i][0] + bp[0];
            o0.y = acc[i][1] + bp[1];
            o0.z = acc[i][2] + bp[2];
            o0.w = acc[i][3] + bp[3];
            o1.x = acc[i][4] + bp[4];
            o1.y = acc[i][5] + bp[5];
            o1.z = acc[i][6] + bp[6];
            o1.w = acc[i][7] + bp[7];
            *(float4*)dst = o0;
            *(float4*)(dst + 4) = o1;
        }
    } else {
        // qkv scatter: n -> (s, h, d); column span per thread is 8, 64-aligned
        // so s,h constant per thread.
        int n0 = bn + tc * 8;
        int s = n0 >> 10;          // 0..2
        int h = (n0 >> 6) & 15;    // head
        int d = n0 & 63;           // 0..56 step 8
        float* base = (s == 0) ? g_q : (s == 1) ? g_k : g_v;
#pragma unroll
        for (int i = 0; i < 8; i++) {
            int m = bm + tr * 8 + i;
            int b = m >> 11;       // T_=2048
            int t = m & (T_ - 1);
            float* dst = base + (((size_t)(b * H_ + h)) * T_ + t) * HD_ + d;
            float4 o0, o1;
            o0.x = acc[i][0];
            o0.y = acc[i][1];
            o0.z = acc[i][2];
            o0.w = acc[i][3];
            o1.x = acc[i][4];
            o1.y = acc[i][5];
            o1.z = acc[i][6];
            o1.w = acc[i][7];
            *(float4*)dst = o0;
            *(float4*)(dst + 4) = o1;
        }
    }
}

// ---------------------------------------------------------------------------
// Flash-style causal local attention.
// Block: one (b,h) x 128-query tile. 128 threads, each owns 8 rows x 8 cols.
// Online softmax. Output written to g_att in (B,T,H*hd) layout.
// ---------------------------------------------------------------------------
#define QTILE 128
#define KTILE 64
#define QLD 128   // Qs[d][m]
#define KLD 65    // Ks[d][n]
#define VLD 64    // Vs[n][d]
#define PLD 129   // Ps[n][m]

#define SM_Q 0
#define SM_K (SM_Q + 64 * QLD)          // 8192
#define SM_V (SM_K + 64 * KLD)          // +4160
#define SM_P (SM_V + 64 * VLD)          // +4096
#define SM_BIAS (SM_P + 64 * PLD)       // +8256
#define SMEM_FLOATS (SM_BIAS + 260)
#define SMEM_BYTES (SMEM_FLOATS * 4)

__global__ __launch_bounds__(128, 2)
void attn_kernel(const float* __restrict__ rel_bias) {
    extern __shared__ float sm[];
    float* Qs = sm + SM_Q;
    float* Ks = sm + SM_K;
    float* Vs = sm + SM_V;
    float* Ps = sm + SM_P;
    float* sb = sm + SM_BIAS;

    const int tid = threadIdx.x;
    const int bh = blockIdx.y;
    const int b = bh >> 4;
    const int h = bh & 15;
    const int q0 = blockIdx.x * QTILE;

    const float* qg = g_q + (size_t)bh * T_ * HD_;
    const float* kg = g_k + (size_t)bh * T_ * HD_;
    const float* vg = g_v + (size_t)bh * T_ * HD_;

    // relative bias LUT for this head
    for (int r = tid; r < NBIAS_; r += 128) sb[r] = rel_bias[r * H_ + h];

    // Load Q tile transposed: Qs[d][m], m in [0,128), d in [0,64)
#pragma unroll
    for (int it = 0; it < 16; it++) {
        int idx = tid + it * 128;
        int row = idx >> 4;           // 0..127
        int d4 = (idx & 15) << 2;     // 0..60 step 4
        float4 v = *(const float4*)(qg + (size_t)(q0 + row) * HD_ + d4);
        Qs[(d4 + 0) * QLD + row] = v.x;
        Qs[(d4 + 1) * QLD + row] = v.y;
        Qs[(d4 + 2) * QLD + row] = v.z;
        Qs[(d4 + 3) * QLD + row] = v.w;
    }
    __syncthreads();

    const int tr = tid >> 3;  // 0..15
    const int tc = tid & 7;   // 0..7
    const int r0 = tr * 8;    // local row base
    const int c0 = tc * 8;    // local col base (keys / dims)

    float o[8][8];
    float mrow[8], lrow[8];
#pragma unroll
    for (int i = 0; i < 8; i++) {
        mrow[i] = -1e30f;
        lrow[i] = 0.f;
#pragma unroll
        for (int j = 0; j < 8; j++) o[i][j] = 0.f;
    }

    int kt_lo = q0 - WIN_;
    if (kt_lo < 0) kt_lo = 0;
    const int kt_hi = q0 + QTILE - KTILE;

    for (int kt = kt_lo; kt <= kt_hi; kt += KTILE) {
        __syncthreads();  // protect Ks/Vs/Ps from previous iteration's readers
        // Load K (transposed) and V (natural)
#pragma unroll
        for (int it = 0; it < 8; it++) {
            int idx = tid + it * 128;
            int row = idx >> 4;         // 0..63
            int d4 = (idx & 15) << 2;   // 0..60 step 4
            float4 kv = *(const float4*)(kg + (size_t)(kt + row) * HD_ + d4);
            Ks[(d4 + 0) * KLD + row] = kv.x;
            Ks[(d4 + 1) * KLD + row] = kv.y;
            Ks[(d4 + 2) * KLD + row] = kv.z;
            Ks[(d4 + 3) * KLD + row] = kv.w;
            float4 vv = *(const float4*)(vg + (size_t)(kt + row) * HD_ + d4);
            *(float4*)(Vs + row * VLD + d4) = vv;
        }
        __syncthreads();

        // S = Q K^T  (8x8 per thread)
        float s[8][8];
#pragma unroll
        for (int i = 0; i < 8; i++)
#pragma unroll
            for (int j = 0; j < 8; j++) s[i][j] = 0.f;
#pragma unroll 8
        for (int d = 0; d < 64; d++) {
            float4 a0 = *(const float4*)(Qs + d * QLD + r0);
            float4 a1 = *(const float4*)(Qs + d * QLD + r0 + 4);
            float a[8] = {a0.x, a0.y, a0.z, a0.w, a1.x, a1.y, a1.z, a1.w};
            float bb[8];
#pragma unroll
            for (int j = 0; j < 8; j++) bb[j] = Ks[d * KLD + c0 + j];
#pragma unroll
            for (int i = 0; i < 8; i++)
#pragma unroll
                for (int j = 0; j < 8; j++) s[i][j] += a[i] * bb[j];
        }

        // mask + bias + online softmax update
#pragma unroll
        for (int i = 0; i < 8; i++) {
            int gi = q0 + r0 + i;
            float mx = -1e30f;
#pragma unroll
            for (int j = 0; j < 8; j++) {
                int gj = kt + c0 + j;
                int dd = gi - gj;
                float val;
                if (dd >= 0 && dd <= WIN_) {
                    int r = (dd > MAXREL_) ? (2 * MAXREL_) : (dd + MAXREL_);
                    val = s[i][j] * 0.125f + sb[r];
                } else {
                    val = -1e30f;
                }
                s[i][j] = val;
                mx = fmaxf(mx, val);
            }
#pragma unroll
            for (int off = 4; off; off >>= 1)
                mx = fmaxf(mx, __shfl_xor_sync(0xffffffffu, mx, off));
            float mn = fmaxf(mrow[i], mx);
            float alpha = __expf(mrow[i] - mn);
            mrow[i] = mn;
            float ps = 0.f;
#pragma unroll
            for (int j = 0; j < 8; j++) {
                float p = (s[i][j] > -1e29f) ? __expf(s[i][j] - mn) : 0.f;
                s[i][j] = p;
                ps += p;
            }
#pragma unroll
            for (int off = 4; off; off >>= 1)
                ps += __shfl_xor_sync(0xffffffffu, ps, off);
            lrow[i] = lrow[i] * alpha + ps;
#pragma unroll
            for (int j = 0; j < 8; j++) o[i][j] *= alpha;
        }

        // write P transposed to smem: Ps[n][m]
#pragma unroll
        for (int j = 0; j < 8; j++)
#pragma unroll
            for (int i = 0; i < 8; i++)
                Ps[(c0 + j) * PLD + r0 + i] = s[i][j];
        __syncthreads();

        // O += P V   (8 rows x 8 dims per thread)
#pragma unroll 8
        for (int n = 0; n < 64; n++) {
            float a[8];
#pragma unroll
            for (int i = 0; i < 8; i++) a[i] = Ps[n * PLD + r0 + i];
            float4 b0 = *(const float4*)(Vs + n * VLD + c0);
            float4 b1 = *(const float4*)(Vs + n * VLD + c0 + 4);
            float bb[8] = {b0.x, b0.y, b0.z, b0.w, b1.x, b1.y, b1.z, b1.w};
#pragma unroll
            for (int i = 0; i < 8; i++)
#pragma unroll
                for (int j = 0; j < 8; j++) o[i][j] += a[i] * bb[j];
        }
    }

    // normalize and write to g_att (B, T, H*hd)
#pragma unroll
    for (int i = 0; i < 8; i++) {
        float inv = 1.f / lrow[i];
        int gi = q0 + r0 + i;
        float* dst = g_att + ((size_t)(b * T_ + gi)) * C_ + h * HD_ + c0;
        float4 o0, o1;
        o0.x = o[i][0] * inv;
        o0.y = o[i][1] * inv;
        o0.z = o[i][2] * inv;
        o0.w = o[i][3] * inv;
        o1.x = o[i][4] * inv;
        o1.y = o[i][5] * inv;
        o1.z = o[i][6] * inv;
        o1.w = o[i][7] * inv;
        *(float4*)dst = o0;
        *(float4*)(dst + 4) = o1;
    }
}

// ---------------------------------------------------------------------------
extern "C" void kernel_launch(void* const* d_in, const int* in_sizes, int n_in,
                              void* d_out, int out_size) {
    // Identify inputs by element count (robust to metadata ordering):
    //   x:        B*T*C        = 4,194,304
    //   w_qkv:    3C*C         = 3,145,728
    //   w_proj:   C*C          = 1,048,576
    //   b_proj:   C            = 1,024
    //   rel_bias: 257*H        = 4,112
    const float* x = nullptr;
    const float* w_qkv = nullptr;
    const float* w_proj = nullptr;
    const float* b_proj = nullptr;
    const float* rel_bias = nullptr;
    for (int i = 0; i < n_in; i++) {
        switch (in_sizes[i]) {
            case 4194304: x = (const float*)d_in[i]; break;
            case 3145728: w_qkv = (const float*)d_in[i]; break;
            case 1048576: w_proj = (const float*)d_in[i]; break;
            case 1024:    b_proj = (const float*)d_in[i]; break;
            case 4112:    rel_bias = (const float*)d_in[i]; break;
            default: break;
        }
    }
    float* out = (float*)d_out;                     // (B,T,C)

    // CRITICAL: resolve the DEVICE address of g_att. Referencing the
    // __device__ symbol directly in host code yields the host shadow
    // variable; on GB300 (ATS) the GPU silently reads host zeros.
    float* att_dev = nullptr;
    cudaGetSymbolAddress((void**)&att_dev, g_att);

    const int M = B_ * T_;  // 4096

    // 1) QKV projection with scatter epilogue
    {
        dim3 grid((3 * C_) / 128, M / 128);
        sgemm_nt<1><<<grid, 256>>>(x, w_qkv, nullptr, nullptr, M, 3 * C_, C_);
    }

    // 2) Local causal attention
    {
        cudaFuncSetAttribute(attn_kernel,
                             cudaFuncAttributeMaxDynamicSharedMemorySize,
                             SMEM_BYTES);
        dim3 grid(T_ / QTILE, B_ * H_);
        attn_kernel<<<grid, 128, SMEM_BYTES>>>(rel_bias);
    }

    // 3) Output projection + bias
    {
        dim3 grid(C_ / 128, M / 128);
        sgemm_nt<0><<<grid, 256>>>(att_dev, w_proj, b_proj, out, M, C_, C_);
    }
}

// round 5
// speedup vs baseline: 1.3299x; 1.3299x over previous
#include <cuda_runtime.h>
#include <cstdint>

// Problem constants
#define B_ 2
#define T_ 2048
#define C_ 1024
#define H_ 16
#define HD_ 64
#define WIN_ 512
#define MAXREL_ 128
#define NBIAS_ 257

// Scratch (device globals; no allocation allowed)
__device__ float g_q[(size_t)B_ * H_ * T_ * HD_];
__device__ float g_k[(size_t)B_ * H_ * T_ * HD_];
__device__ float g_v[(size_t)B_ * H_ * T_ * HD_];
__device__ float g_att[(size_t)B_ * T_ * C_];

// ---------------------------------------------------------------------------
// tf32 helpers
// ---------------------------------------------------------------------------
__device__ __forceinline__ uint32_t f2tf(float a) {
    uint32_t r;
    asm("cvt.rna.tf32.f32 %0, %1;" : "=r"(r) : "f"(a));
    return r;
}

__device__ __forceinline__ void mma_tf32(float c[4], const uint32_t a[4],
                                         const uint32_t b[2]) {
    asm("mma.sync.aligned.m16n8k8.row.col.f32.tf32.tf32.f32 "
        "{%0,%1,%2,%3}, {%4,%5,%6,%7}, {%8,%9}, {%0,%1,%2,%3};"
        : "+f"(c[0]), "+f"(c[1]), "+f"(c[2]), "+f"(c[3])
        : "r"(a[0]), "r"(a[1]), "r"(a[2]), "r"(a[3]), "r"(b[0]), "r"(b[1]));
}

// ---------------------------------------------------------------------------
// TF32 tensor-core GEMM NT: C[m][n] = sum_k A[m][k] * B[n][k]
// BM=BN=128, BK=16, 256 threads (8 warps, 4x2), warp tile 32x64.
// SPLIT=3: 3xTF32 error-compensated (fp32-class accuracy).
// SPLIT=1: plain tf32.
// MODE 0: C = acc + bias[n].  MODE 1: QKV scatter epilogue.
// Smem layout (uint2 units): per source (A then B):
//   [buf(2)][plane(PLANES)][ (s*4+c)*LDSM + row ]  where element (row,k):
//   k = 8*s + c + 4*u, u selects .x/.y of the uint2. Fragment loads are LDS.64.
// ---------------------------------------------------------------------------
#define LDSM 136   // uint2 row stride (128 + 8 pad)

template <int SPLIT>
__device__ __forceinline__ void store_plane(uint2* buf0, const float4 r0,
                                            const float4 r1, int grow, int gs,
                                            int gu) {
    const float* v0 = &r0.x;
    const float* v1 = &r1.x;
#pragma unroll
    for (int e = 0; e < 4; e++) {
        uint32_t h0 = f2tf(v0[e]);
        uint32_t h1 = f2tf(v1[e]);
        ((uint32_t*)&buf0[(gs * 4 + e) * LDSM + grow])[gu] = h0;
        ((uint32_t*)&buf0[(gs * 4 + e) * LDSM + grow + 64])[gu] = h1;
        if (SPLIT == 3) {
            uint32_t l0 = f2tf(v0[e] - __uint_as_float(h0));
            uint32_t l1 = f2tf(v1[e] - __uint_as_float(h1));
            ((uint32_t*)&buf0[8 * LDSM + (gs * 4 + e) * LDSM + grow])[gu] = l0;
            ((uint32_t*)&buf0[8 * LDSM + (gs * 4 + e) * LDSM + grow + 64])[gu] = l1;
        }
    }
}

template <int MODE, int SPLIT>
__global__ __launch_bounds__(256, 2)
void gemm_tf32(const float* __restrict__ A, const float* __restrict__ Bm,
               const float* __restrict__ bias, float* __restrict__ Cout,
               int N, int K) {
    constexpr int PLANES = (SPLIT == 3) ? 2 : 1;
    constexpr int SRC = PLANES * 8 * LDSM;   // uint2 per (buf,source)
    extern __shared__ uint2 smem[];
    uint2* Asm = smem;                 // [2][SRC]
    uint2* Bsm = smem + 2 * SRC;       // [2][SRC]

    const int tid = threadIdx.x;
    const int warp = tid >> 5, lane = tid & 31;
    const int wm = warp & 3, wn = warp >> 2;     // 4 x 2 warp grid
    const int gid = lane >> 2, tig = lane & 3;
    const int bm = blockIdx.y * 128, bn = blockIdx.x * 128;

    const int grow = tid >> 2;   // 0..63
    const int gt = tid & 3;
    const int gs = gt >> 1, gu = gt & 1;

    const float* Ag = A + (size_t)(bm + grow) * K + gt * 4;
    const float* Ag2 = Ag + (size_t)64 * K;
    const float* Bg = Bm + (size_t)(bn + grow) * K + gt * 4;
    const float* Bg2 = Bg + (size_t)64 * K;

    float acc[2][8][4];
#pragma unroll
    for (int i = 0; i < 2; i++)
#pragma unroll
        for (int j = 0; j < 8; j++)
#pragma unroll
            for (int e = 0; e < 4; e++) acc[i][j][e] = 0.f;

    const int NT = K >> 4;

    float4 ra0 = *(const float4*)(Ag);
    float4 ra1 = *(const float4*)(Ag2);
    float4 rb0 = *(const float4*)(Bg);
    float4 rb1 = *(const float4*)(Bg2);
    store_plane<SPLIT>(Asm, ra0, ra1, grow, gs, gu);
    store_plane<SPLIT>(Bsm, rb0, rb1, grow, gs, gu);
    __syncthreads();

    int buf = 0;
    for (int kt = 0; kt < NT; kt++) {
        if (kt + 1 < NT) {
            int off = (kt + 1) * 16;
            ra0 = *(const float4*)(Ag + off);
            ra1 = *(const float4*)(Ag2 + off);
            rb0 = *(const float4*)(Bg + off);
            rb1 = *(const float4*)(Bg2 + off);
        }
        const uint2* Ab = Asm + buf * SRC;
        const uint2* Bb = Bsm + buf * SRC;
#pragma unroll
        for (int s = 0; s < 2; s++) {
            uint32_t ah[2][4], al[2][4];
#pragma unroll
            for (int i = 0; i < 2; i++) {
                int m0 = wm * 32 + i * 16 + gid;
                uint2 lo = Ab[(s * 4 + tig) * LDSM + m0];
                uint2 hi = Ab[(s * 4 + tig) * LDSM + m0 + 8];
                ah[i][0] = lo.x; ah[i][1] = hi.x;
                ah[i][2] = lo.y; ah[i][3] = hi.y;
                if (SPLIT == 3) {
                    uint2 lo2 = Ab[8 * LDSM + (s * 4 + tig) * LDSM + m0];
                    uint2 hi2 = Ab[8 * LDSM + (s * 4 + tig) * LDSM + m0 + 8];
                    al[i][0] = lo2.x; al[i][1] = hi2.x;
                    al[i][2] = lo2.y; al[i][3] = hi2.y;
                }
            }
#pragma unroll
            for (int j = 0; j < 8; j++) {
                int n0 = wn * 64 + j * 8 + gid;
                uint2 bv = Bb[(s * 4 + tig) * LDSM + n0];
                uint32_t bh[2] = {bv.x, bv.y};
#pragma unroll
                for (int i = 0; i < 2; i++) mma_tf32(acc[i][j], ah[i], bh);
                if (SPLIT == 3) {
                    uint2 bv2 = Bb[8 * LDSM + (s * 4 + tig) * LDSM + n0];
                    uint32_t bl[2] = {bv2.x, bv2.y};
#pragma unroll
                    for (int i = 0; i < 2; i++) {
                        mma_tf32(acc[i][j], al[i], bh);
                        mma_tf32(acc[i][j], ah[i], bl);
                    }
                }
            }
        }
        if (kt + 1 < NT) {
            uint2* An = Asm + (buf ^ 1) * SRC;
            uint2* Bn = Bsm + (buf ^ 1) * SRC;
            store_plane<SPLIT>(An, ra0, ra1, grow, gs, gu);
            store_plane<SPLIT>(Bn, rb0, rb1, grow, gs, gu);
        }
        __syncthreads();
        buf ^= 1;
    }

    // Epilogue
#pragma unroll
    for (int i = 0; i < 2; i++) {
#pragma unroll
        for (int j = 0; j < 8; j++) {
            int nb = bn + wn * 64 + j * 8 + tig * 2;   // even
            int m1 = bm + wm * 32 + i * 16 + gid;
            if (MODE == 0) {
                float2 bb = *(const float2*)(bias + nb);
                float2 v0, v1;
                v0.x = acc[i][j][0] + bb.x; v0.y = acc[i][j][1] + bb.y;
                v1.x = acc[i][j][2] + bb.x; v1.y = acc[i][j][3] + bb.y;
                *(float2*)(Cout + (size_t)m1 * N + nb) = v0;
                *(float2*)(Cout + (size_t)(m1 + 8) * N + nb) = v1;
            } else {
                int s = nb >> 10;
                int h = (nb >> 6) & 15;
                int d = nb & 63;
                float* base = (s == 0) ? g_q : (s == 1) ? g_k : g_v;
                int b = m1 >> 11, t = m1 & (T_ - 1);
                float* dst = base + (((size_t)(b * H_ + h)) * T_ + t) * HD_ + d;
                float* dst2 = base + (((size_t)(b * H_ + h)) * T_ + t + 8) * HD_ + d;
                float2 v0, v1;
                v0.x = acc[i][j][0]; v0.y = acc[i][j][1];
                v1.x = acc[i][j][2]; v1.y = acc[i][j][3];
                *(float2*)dst = v0;
                *(float2*)dst2 = v1;
            }
        }
    }
}

// ---------------------------------------------------------------------------
// Flash-style causal local attention (unchanged from R4 passing version).
// ---------------------------------------------------------------------------
#define QTILE 128
#define KTILE 64
#define QLD 128
#define KLD 65
#define VLD 64
#define PLD 129

#define SM_Q 0
#define SM_K (SM_Q + 64 * QLD)
#define SM_V (SM_K + 64 * KLD)
#define SM_P (SM_V + 64 * VLD)
#define SM_BIAS (SM_P + 64 * PLD)
#define SMEM_FLOATS (SM_BIAS + 260)
#define SMEM_BYTES (SMEM_FLOATS * 4)

__global__ __launch_bounds__(128, 2)
void attn_kernel(const float* __restrict__ rel_bias) {
    extern __shared__ float sm[];
    float* Qs = sm + SM_Q;
    float* Ks = sm + SM_K;
    float* Vs = sm + SM_V;
    float* Ps = sm + SM_P;
    float* sb = sm + SM_BIAS;

    const int tid = threadIdx.x;
    const int bh = blockIdx.y;
    const int b = bh >> 4;
    const int h = bh & 15;
    const int q0 = blockIdx.x * QTILE;

    const float* qg = g_q + (size_t)bh * T_ * HD_;
    const float* kg = g_k + (size_t)bh * T_ * HD_;
    const float* vg = g_v + (size_t)bh * T_ * HD_;

    for (int r = tid; r < NBIAS_; r += 128) sb[r] = rel_bias[r * H_ + h];

#pragma unroll
    for (int it = 0; it < 16; it++) {
        int idx = tid + it * 128;
        int row = idx >> 4;
        int d4 = (idx & 15) << 2;
        float4 v = *(const float4*)(qg + (size_t)(q0 + row) * HD_ + d4);
        Qs[(d4 + 0) * QLD + row] = v.x;
        Qs[(d4 + 1) * QLD + row] = v.y;
        Qs[(d4 + 2) * QLD + row] = v.z;
        Qs[(d4 + 3) * QLD + row] = v.w;
    }
    __syncthreads();

    const int tr = tid >> 3;
    const int tc = tid & 7;
    const int r0 = tr * 8;
    const int c0 = tc * 8;

    float o[8][8];
    float mrow[8], lrow[8];
#pragma unroll
    for (int i = 0; i < 8; i++) {
        mrow[i] = -1e30f;
        lrow[i] = 0.f;
#pragma unroll
        for (int j = 0; j < 8; j++) o[i][j] = 0.f;
    }

    int kt_lo = q0 - WIN_;
    if (kt_lo < 0) kt_lo = 0;
    const int kt_hi = q0 + QTILE - KTILE;

    for (int kt = kt_lo; kt <= kt_hi; kt += KTILE) {
        __syncthreads();
#pragma unroll
        for (int it = 0; it < 8; it++) {
            int idx = tid + it * 128;
            int row = idx >> 4;
            int d4 = (idx & 15) << 2;
            float4 kv = *(const float4*)(kg + (size_t)(kt + row) * HD_ + d4);
            Ks[(d4 + 0) * KLD + row] = kv.x;
            Ks[(d4 + 1) * KLD + row] = kv.y;
            Ks[(d4 + 2) * KLD + row] = kv.z;
            Ks[(d4 + 3) * KLD + row] = kv.w;
            float4 vv = *(const float4*)(vg + (size_t)(kt + row) * HD_ + d4);
            *(float4*)(Vs + row * VLD + d4) = vv;
        }
        __syncthreads();

        float s[8][8];
#pragma unroll
        for (int i = 0; i < 8; i++)
#pragma unroll
            for (int j = 0; j < 8; j++) s[i][j] = 0.f;
#pragma unroll 8
        for (int d = 0; d < 64; d++) {
            float4 a0 = *(const float4*)(Qs + d * QLD + r0);
            float4 a1 = *(const float4*)(Qs + d * QLD + r0 + 4);
            float a[8] = {a0.x, a0.y, a0.z, a0.w, a1.x, a1.y, a1.z, a1.w};
            float bb[8];
#pragma unroll
            for (int j = 0; j < 8; j++) bb[j] = Ks[d * KLD + c0 + j];
#pragma unroll
            for (int i = 0; i < 8; i++)
#pragma unroll
                for (int j = 0; j < 8; j++) s[i][j] += a[i] * bb[j];
        }

#pragma unroll
        for (int i = 0; i < 8; i++) {
            int gi = q0 + r0 + i;
            float mx = -1e30f;
#pragma unroll
            for (int j = 0; j < 8; j++) {
                int gj = kt + c0 + j;
                int dd = gi - gj;
                float val;
                if (dd >= 0 && dd <= WIN_) {
                    int r = (dd > MAXREL_) ? (2 * MAXREL_) : (dd + MAXREL_);
                    val = s[i][j] * 0.125f + sb[r];
                } else {
                    val = -1e30f;
                }
                s[i][j] = val;
                mx = fmaxf(mx, val);
            }
#pragma unroll
            for (int off = 4; off; off >>= 1)
                mx = fmaxf(mx, __shfl_xor_sync(0xffffffffu, mx, off));
            float mn = fmaxf(mrow[i], mx);
            float alpha = __expf(mrow[i] - mn);
            mrow[i] = mn;
            float ps = 0.f;
#pragma unroll
            for (int j = 0; j < 8; j++) {
                float p = (s[i][j] > -1e29f) ? __expf(s[i][j] - mn) : 0.f;
                s[i][j] = p;
                ps += p;
            }
#pragma unroll
            for (int off = 4; off; off >>= 1)
                ps += __shfl_xor_sync(0xffffffffu, ps, off);
            lrow[i] = lrow[i] * alpha + ps;
#pragma unroll
            for (int j = 0; j < 8; j++) o[i][j] *= alpha;
        }

#pragma unroll
        for (int j = 0; j < 8; j++)
#pragma unroll
            for (int i = 0; i < 8; i++)
                Ps[(c0 + j) * PLD + r0 + i] = s[i][j];
        __syncthreads();

#pragma unroll 8
        for (int n = 0; n < 64; n++) {
            float a[8];
#pragma unroll
            for (int i = 0; i < 8; i++) a[i] = Ps[n * PLD + r0 + i];
            float4 b0 = *(const float4*)(Vs + n * VLD + c0);
            float4 b1 = *(const float4*)(Vs + n * VLD + c0 + 4);
            float bb[8] = {b0.x, b0.y, b0.z, b0.w, b1.x, b1.y, b1.z, b1.w};
#pragma unroll
            for (int i = 0; i < 8; i++)
#pragma unroll
                for (int j = 0; j < 8; j++) o[i][j] += a[i] * bb[j];
        }
    }

#pragma unroll
    for (int i = 0; i < 8; i++) {
        float inv = 1.f / lrow[i];
        int gi = q0 + r0 + i;
        float* dst = g_att + ((size_t)(b * T_ + gi)) * C_ + h * HD_ + c0;
        float4 o0, o1;
        o0.x = o[i][0] * inv;
        o0.y = o[i][1] * inv;
        o0.z = o[i][2] * inv;
        o0.w = o[i][3] * inv;
        o1.x = o[i][4] * inv;
        o1.y = o[i][5] * inv;
        o1.z = o[i][6] * inv;
        o1.w = o[i][7] * inv;
        *(float4*)dst = o0;
        *(float4*)(dst + 4) = o1;
    }
}

// ---------------------------------------------------------------------------
extern "C" void kernel_launch(void* const* d_in, const int* in_sizes, int n_in,
                              void* d_out, int out_size) {
    // Identify inputs by element count (robust to metadata ordering)
    const float* x = nullptr;
    const float* w_qkv = nullptr;
    const float* w_proj = nullptr;
    const float* b_proj = nullptr;
    const float* rel_bias = nullptr;
    for (int i = 0; i < n_in; i++) {
        switch (in_sizes[i]) {
            case 4194304: x = (const float*)d_in[i]; break;
            case 3145728: w_qkv = (const float*)d_in[i]; break;
            case 1048576: w_proj = (const float*)d_in[i]; break;
            case 1024:    b_proj = (const float*)d_in[i]; break;
            case 4112:    rel_bias = (const float*)d_in[i]; break;
            default: break;
        }
    }
    float* out = (float*)d_out;

    // Resolve DEVICE address of g_att (host shadow trap on ATS systems).
    float* att_dev = nullptr;
    cudaGetSymbolAddress((void**)&att_dev, g_att);

    const int M = B_ * T_;  // 4096

    // Dynamic smem sizes (uint2 units -> bytes)
    const int smem3 = 2 * (2 * 2 * 8 * LDSM) * 8;  // SPLIT=3: A+B, 2 buf, 2 planes
    const int smem1 = 2 * (2 * 1 * 8 * LDSM) * 8;  // SPLIT=1

    // 1) QKV projection, 3xTF32 tensor cores, scatter epilogue
    {
        cudaFuncSetAttribute(gemm_tf32<1, 3>,
                             cudaFuncAttributeMaxDynamicSharedMemorySize, smem3);
        dim3 grid((3 * C_) / 128, M / 128);
        gemm_tf32<1, 3><<<grid, 256, smem3>>>(x, w_qkv, nullptr, nullptr,
                                              3 * C_, C_);
    }

    // 2) Local causal attention (fp32)
    {
        cudaFuncSetAttribute(attn_kernel,
                             cudaFuncAttributeMaxDynamicSharedMemorySize,
                             SMEM_BYTES);
        dim3 grid(T_ / QTILE, B_ * H_);
        attn_kernel<<<grid, 128, SMEM_BYTES>>>(rel_bias);
    }

    // 3) Output projection + bias, plain tf32
    {
        cudaFuncSetAttribute(gemm_tf32<0, 1>,
                             cudaFuncAttributeMaxDynamicSharedMemorySize, smem1);
        dim3 grid(C_ / 128, M / 128);
        gemm_tf32<0, 1><<<grid, 256, smem1>>>(att_dev, w_proj, b_proj, out,
                                              C_, C_);
    }
}

// round 9
// speedup vs baseline: 2.1348x; 1.6052x over previous
#include <cuda_runtime.h>
#include <cstdint>

// Problem constants
#define B_ 2
#define T_ 2048
#define C_ 1024
#define H_ 16
#define HD_ 64
#define WIN_ 512
#define MAXREL_ 128
#define NBIAS_ 257

// Scratch (device globals; no allocation allowed)
__device__ float g_q[(size_t)B_ * H_ * T_ * HD_];
__device__ float g_k[(size_t)B_ * H_ * T_ * HD_];
__device__ float g_v[(size_t)B_ * H_ * T_ * HD_];
__device__ float g_att[(size_t)B_ * T_ * C_];

// ---------------------------------------------------------------------------
// tf32 helpers
// ---------------------------------------------------------------------------
__device__ __forceinline__ uint32_t f2tf(float a) {
    uint32_t r;
    asm("cvt.rna.tf32.f32 %0, %1;" : "=r"(r) : "f"(a));
    return r;
}

__device__ __forceinline__ void mma_tf32(float c[4], const uint32_t a[4],
                                         const uint32_t b[2]) {
    asm("mma.sync.aligned.m16n8k8.row.col.f32.tf32.tf32.f32 "
        "{%0,%1,%2,%3}, {%4,%5,%6,%7}, {%8,%9}, {%0,%1,%2,%3};"
        : "+f"(c[0]), "+f"(c[1]), "+f"(c[2]), "+f"(c[3])
        : "r"(a[0]), "r"(a[1]), "r"(a[2]), "r"(a[3]), "r"(b[0]), "r"(b[1]));
}

// ---------------------------------------------------------------------------
// TF32 tensor-core GEMM NT: C[m][n] = sum_k A[m][k] * B[n][k]
// BM=BN=128, BK=16, 256 threads (8 warps, 4x2), warp tile 32x64.
// SPLIT=3: 3xTF32 error-compensated.  SPLIT=1: plain tf32.
// MODE 0: C = acc + bias[n].  MODE 1: QKV scatter epilogue.
// ---------------------------------------------------------------------------
#define LDSM 136   // uint2 row stride (128 + 8 pad)

template <int SPLIT>
__device__ __forceinline__ void store_plane(uint2* buf0, const float4 r0,
                                            const float4 r1, int grow, int gs,
                                            int gu) {
    const float* v0 = &r0.x;
    const float* v1 = &r1.x;
#pragma unroll
    for (int e = 0; e < 4; e++) {
        uint32_t h0 = f2tf(v0[e]);
        uint32_t h1 = f2tf(v1[e]);
        ((uint32_t*)&buf0[(gs * 4 + e) * LDSM + grow])[gu] = h0;
        ((uint32_t*)&buf0[(gs * 4 + e) * LDSM + grow + 64])[gu] = h1;
        if (SPLIT == 3) {
            uint32_t l0 = f2tf(v0[e] - __uint_as_float(h0));
            uint32_t l1 = f2tf(v1[e] - __uint_as_float(h1));
            ((uint32_t*)&buf0[8 * LDSM + (gs * 4 + e) * LDSM + grow])[gu] = l0;
            ((uint32_t*)&buf0[8 * LDSM + (gs * 4 + e) * LDSM + grow + 64])[gu] = l1;
        }
    }
}

template <int MODE, int SPLIT>
__global__ __launch_bounds__(256, 2)
void gemm_tf32(const float* __restrict__ A, const float* __restrict__ Bm,
               const float* __restrict__ bias, float* __restrict__ Cout,
               int N, int K) {
    constexpr int PLANES = (SPLIT == 3) ? 2 : 1;
    constexpr int SRC = PLANES * 8 * LDSM;   // uint2 per (buf,source)
    extern __shared__ uint2 smem[];
    uint2* Asm = smem;                 // [2][SRC]
    uint2* Bsm = smem + 2 * SRC;       // [2][SRC]

    const int tid = threadIdx.x;
    const int warp = tid >> 5, lane = tid & 31;
    const int wm = warp & 3, wn = warp >> 2;     // 4 x 2 warp grid
    const int gid = lane >> 2, tig = lane & 3;
    const int bm = blockIdx.y * 128, bn = blockIdx.x * 128;

    const int grow = tid >> 2;   // 0..63
    const int gt = tid & 3;
    const int gs = gt >> 1, gu = gt & 1;

    const float* Ag = A + (size_t)(bm + grow) * K + gt * 4;
    const float* Ag2 = Ag + (size_t)64 * K;
    const float* Bg = Bm + (size_t)(bn + grow) * K + gt * 4;
    const float* Bg2 = Bg + (size_t)64 * K;

    float acc[2][8][4];
#pragma unroll
    for (int i = 0; i < 2; i++)
#pragma unroll
        for (int j = 0; j < 8; j++)
#pragma unroll
            for (int e = 0; e < 4; e++) acc[i][j][e] = 0.f;

    const int NT = K >> 4;

    float4 ra0 = *(const float4*)(Ag);
    float4 ra1 = *(const float4*)(Ag2);
    float4 rb0 = *(const float4*)(Bg);
    float4 rb1 = *(const float4*)(Bg2);
    store_plane<SPLIT>(Asm, ra0, ra1, grow, gs, gu);
    store_plane<SPLIT>(Bsm, rb0, rb1, grow, gs, gu);
    __syncthreads();

    int buf = 0;
    for (int kt = 0; kt < NT; kt++) {
        if (kt + 1 < NT) {
            int off = (kt + 1) * 16;
            ra0 = *(const float4*)(Ag + off);
            ra1 = *(const float4*)(Ag2 + off);
            rb0 = *(const float4*)(Bg + off);
            rb1 = *(const float4*)(Bg2 + off);
        }
        const uint2* Ab = Asm + buf * SRC;
        const uint2* Bb = Bsm + buf * SRC;
#pragma unroll
        for (int s = 0; s < 2; s++) {
            uint32_t ah[2][4], al[2][4];
#pragma unroll
            for (int i = 0; i < 2; i++) {
                int m0 = wm * 32 + i * 16 + gid;
                uint2 lo = Ab[(s * 4 + tig) * LDSM + m0];
                uint2 hi = Ab[(s * 4 + tig) * LDSM + m0 + 8];
                ah[i][0] = lo.x; ah[i][1] = hi.x;
                ah[i][2] = lo.y; ah[i][3] = hi.y;
                if (SPLIT == 3) {
                    uint2 lo2 = Ab[8 * LDSM + (s * 4 + tig) * LDSM + m0];
                    uint2 hi2 = Ab[8 * LDSM + (s * 4 + tig) * LDSM + m0 + 8];
                    al[i][0] = lo2.x; al[i][1] = hi2.x;
                    al[i][2] = lo2.y; al[i][3] = hi2.y;
                }
            }
#pragma unroll
            for (int j = 0; j < 8; j++) {
                int n0 = wn * 64 + j * 8 + gid;
                uint2 bv = Bb[(s * 4 + tig) * LDSM + n0];
                uint32_t bh[2] = {bv.x, bv.y};
#pragma unroll
                for (int i = 0; i < 2; i++) mma_tf32(acc[i][j], ah[i], bh);
                if (SPLIT == 3) {
                    uint2 bv2 = Bb[8 * LDSM + (s * 4 + tig) * LDSM + n0];
                    uint32_t bl[2] = {bv2.x, bv2.y};
#pragma unroll
                    for (int i = 0; i < 2; i++) {
                        mma_tf32(acc[i][j], al[i], bh);
                        mma_tf32(acc[i][j], ah[i], bl);
                    }
                }
            }
        }
        if (kt + 1 < NT) {
            uint2* An = Asm + (buf ^ 1) * SRC;
            uint2* Bn = Bsm + (buf ^ 1) * SRC;
            store_plane<SPLIT>(An, ra0, ra1, grow, gs, gu);
            store_plane<SPLIT>(Bn, rb0, rb1, grow, gs, gu);
        }
        __syncthreads();
        buf ^= 1;
    }

    // Epilogue
#pragma unroll
    for (int i = 0; i < 2; i++) {
#pragma unroll
        for (int j = 0; j < 8; j++) {
            int nb = bn + wn * 64 + j * 8 + tig * 2;   // even
            int m1 = bm + wm * 32 + i * 16 + gid;
            if (MODE == 0) {
                float2 bb = *(const float2*)(bias + nb);
                float2 v0, v1;
                v0.x = acc[i][j][0] + bb.x; v0.y = acc[i][j][1] + bb.y;
                v1.x = acc[i][j][2] + bb.x; v1.y = acc[i][j][3] + bb.y;
                *(float2*)(Cout + (size_t)m1 * N + nb) = v0;
                *(float2*)(Cout + (size_t)(m1 + 8) * N + nb) = v1;
            } else {
                int s = nb >> 10;
                int h = (nb >> 6) & 15;
                int d = nb & 63;
                float* base = (s == 0) ? g_q : (s == 1) ? g_k : g_v;
                int b = m1 >> 11, t = m1 & (T_ - 1);
                float* dst = base + (((size_t)(b * H_ + h)) * T_ + t) * HD_ + d;
                float* dst2 = base + (((size_t)(b * H_ + h)) * T_ + t + 8) * HD_ + d;
                float2 v0, v1;
                v0.x = acc[i][j][0]; v0.y = acc[i][j][1];
                v1.x = acc[i][j][2]; v1.y = acc[i][j][3];
                *(float2*)dst = v0;
                *(float2*)dst2 = v1;
            }
        }
    }
}

// ---------------------------------------------------------------------------
// Tensor-core (tf32 mma) flash attention with causal local window + rel bias.
// 256 threads = 8 warps; q-tile 128 (warp owns 16 rows); k-tile 64.
// Fragment-packed smem: uint2 holds (k, k+4) pair -> 1 LDS.64 per fragment.
// ---------------------------------------------------------------------------
#define QS32 66   // uint32 row stride for Q (33 uint2)
#define KS32 66
#define VS32 132  // uint32 stride per key-pair row (66 uint2)
#define PS32 66

#define OFF_Q 0
#define OFF_K (OFF_Q + 128 * 33)         // u2 units
#define OFF_V (OFF_K + 64 * 33)
#define OFF_P (OFF_V + 32 * 66)
#define OFF_BIAS (OFF_P + 128 * 33)
#define ATT_SMEM_U2 (OFF_BIAS + 130)
#define ATT_SMEM_BYTES (ATT_SMEM_U2 * 8)

__global__ __launch_bounds__(256, 2)
void attn_tc(const float* __restrict__ rel_bias) {
    extern __shared__ uint2 su[];
    uint32_t* Qs = (uint32_t*)(su + OFF_Q);
    uint32_t* Ks = (uint32_t*)(su + OFF_K);
    uint32_t* Vs = (uint32_t*)(su + OFF_V);
    uint32_t* Ps = (uint32_t*)(su + OFF_P);
    float* sb = (float*)(su + OFF_BIAS);

    const int tid = threadIdx.x;
    const int warp = tid >> 5, lane = tid & 31;
    const int g = lane >> 2, tig = lane & 3;
    const int bh = blockIdx.y;
    const int b = bh >> 4, h = bh & 15;
    const int q0 = blockIdx.x * 128;

    const float* qg = g_q + (size_t)bh * T_ * HD_;
    const float* kg = g_k + (size_t)bh * T_ * HD_;
    const float* vg = g_v + (size_t)bh * T_ * HD_;

    for (int r = tid; r < NBIAS_; r += 256) sb[r] = rel_bias[r * H_ + h];

    // Load + convert Q tile: 128 rows x 16 float4 = 2048 float4 (it < 8 !)
#pragma unroll
    for (int it = 0; it < 8; it++) {
        int fi = tid + it * 256;          // 0..2047 float4 index
        int row = fi >> 4;                // 0..127
        int d0 = (fi & 15) << 2;
        float4 v = *(const float4*)(qg + (size_t)(q0 + row) * HD_ + d0);
#pragma unroll
        for (int e = 0; e < 4; e++) {
            int d = d0 + e, s_ = d >> 3, c = d & 7;
            Qs[row * QS32 + (s_ * 4 + (c & 3)) * 2 + (c >> 2)] =
                f2tf(((const float*)&v)[e]);
        }
    }
    __syncthreads();

    const int rg = warp * 16 + g;   // local row within q-tile

    float oreg[8][4];
    float mrow[2], lrow[2];
#pragma unroll
    for (int nt = 0; nt < 8; nt++)
#pragma unroll
        for (int e = 0; e < 4; e++) oreg[nt][e] = 0.f;
    mrow[0] = mrow[1] = -1e30f;
    lrow[0] = lrow[1] = 0.f;

    int kt_lo = q0 - WIN_;
    if (kt_lo < 0) kt_lo = 0;
    const int kt_hi = q0 + 64;

    for (int kt = kt_lo; kt <= kt_hi; kt += 64) {
        __syncthreads();   // protect K/V from previous iteration readers
        // Load + convert K,V tiles (64 rows x 16 float4 = 1024 float4)
#pragma unroll
        for (int it = 0; it < 4; it++) {
            int fi = tid + it * 256;      // 0..1023
            int row = fi >> 4;            // 0..63
            int d0 = (fi & 15) << 2;
            float4 kv = *(const float4*)(kg + (size_t)(kt + row) * HD_ + d0);
            float4 vv = *(const float4*)(vg + (size_t)(kt + row) * HD_ + d0);
            int sk = row >> 3, ck = row & 7;
            int vbase = (sk * 4 + (ck & 3)) * VS32 + (ck >> 2);
#pragma unroll
            for (int e = 0; e < 4; e++) {
                int d = d0 + e, s_ = d >> 3, c = d & 7;
                Ks[row * KS32 + (s_ * 4 + (c & 3)) * 2 + (c >> 2)] =
                    f2tf(((const float*)&kv)[e]);
                Vs[vbase + d * 2] = f2tf(((const float*)&vv)[e]);
            }
        }
        __syncthreads();

        // S = Q K^T (per warp: 16 x 64)
        float sreg[8][4];
#pragma unroll
        for (int j = 0; j < 8; j++)
#pragma unroll
            for (int e = 0; e < 4; e++) sreg[j][e] = 0.f;
#pragma unroll
        for (int s_ = 0; s_ < 8; s_++) {
            uint2 qa0 = *(const uint2*)&Qs[rg * QS32 + (s_ * 4 + tig) * 2];
            uint2 qa1 = *(const uint2*)&Qs[(rg + 8) * QS32 + (s_ * 4 + tig) * 2];
            uint32_t a[4] = {qa0.x, qa1.x, qa0.y, qa1.y};
#pragma unroll
            for (int j = 0; j < 8; j++) {
                uint2 kb = *(const uint2*)&Ks[(8 * j + g) * KS32 + (s_ * 4 + tig) * 2];
                uint32_t bb[2] = {kb.x, kb.y};
                mma_tf32(sreg[j], a, bb);
            }
        }

        // mask + bias + online softmax (rows rg, rg+8; cols 8j+2tig+e)
#pragma unroll
        for (int hi = 0; hi < 2; hi++) {
            int gi = q0 + rg + 8 * hi;
            float mx = -1e30f;
#pragma unroll
            for (int j = 0; j < 8; j++)
#pragma unroll
                for (int e = 0; e < 2; e++) {
                    int key = kt + 8 * j + 2 * tig + e;
                    int dd = gi - key;
                    float val;
                    if (dd >= 0 && dd <= WIN_) {
                        int r = (dd > MAXREL_) ? (2 * MAXREL_) : (dd + MAXREL_);
                        val = sreg[j][2 * hi + e] * 0.125f + sb[r];
                    } else {
                        val = -1e30f;
                    }
                    sreg[j][2 * hi + e] = val;
                    mx = fmaxf(mx, val);
                }
            mx = fmaxf(mx, __shfl_xor_sync(0xffffffffu, mx, 1));
            mx = fmaxf(mx, __shfl_xor_sync(0xffffffffu, mx, 2));
            float mn = fmaxf(mrow[hi], mx);
            float alpha = __expf(mrow[hi] - mn);
            mrow[hi] = mn;
            float ps = 0.f;
#pragma unroll
            for (int j = 0; j < 8; j++)
#pragma unroll
                for (int e = 0; e < 2; e++) {
                    float v = sreg[j][2 * hi + e];
                    float p = (v > -1e29f) ? __expf(v - mn) : 0.f;
                    sreg[j][2 * hi + e] = p;
                    ps += p;
                }
            ps += __shfl_xor_sync(0xffffffffu, ps, 1);
            ps += __shfl_xor_sync(0xffffffffu, ps, 2);
            lrow[hi] = lrow[hi] * alpha + ps;
#pragma unroll
            for (int nt = 0; nt < 8; nt++) {
                oreg[nt][2 * hi] *= alpha;
                oreg[nt][2 * hi + 1] *= alpha;
            }
        }

        // Store P (tf32, packed pairs) for use as A-fragment in PV
#pragma unroll
        for (int j = 0; j < 8; j++)
#pragma unroll
            for (int hi = 0; hi < 2; hi++)
#pragma unroll
                for (int e = 0; e < 2; e++) {
                    int c = 2 * tig + e;
                    Ps[(rg + 8 * hi) * PS32 + (j * 4 + (c & 3)) * 2 + (c >> 2)] =
                        f2tf(sreg[j][2 * hi + e]);
                }
        __syncthreads();

        // O += P V
#pragma unroll
        for (int s_ = 0; s_ < 8; s_++) {
            uint2 pa0 = *(const uint2*)&Ps[rg * PS32 + (s_ * 4 + tig) * 2];
            uint2 pa1 = *(const uint2*)&Ps[(rg + 8) * PS32 + (s_ * 4 + tig) * 2];
            uint32_t a[4] = {pa0.x, pa1.x, pa0.y, pa1.y};
#pragma unroll
            for (int nt = 0; nt < 8; nt++) {
                uint2 vb = *(const uint2*)&Vs[(s_ * 4 + tig) * VS32 + (g + 8 * nt) * 2];
                uint32_t bb[2] = {vb.x, vb.y};
                mma_tf32(oreg[nt], a, bb);
            }
        }
    }

    // Normalize + write out (B, T, H*hd)
#pragma unroll
    for (int hi = 0; hi < 2; hi++) {
        float inv = 1.f / lrow[hi];
        int gi = q0 + rg + 8 * hi;
        float* dst = g_att + ((size_t)(b * T_ + gi)) * C_ + h * HD_;
#pragma unroll
        for (int nt = 0; nt < 8; nt++) {
            float2 v;
            v.x = oreg[nt][2 * hi] * inv;
            v.y = oreg[nt][2 * hi + 1] * inv;
            *(float2*)(dst + 8 * nt + 2 * tig) = v;
        }
    }
}

// ---------------------------------------------------------------------------
extern "C" void kernel_launch(void* const* d_in, const int* in_sizes, int n_in,
                              void* d_out, int out_size) {
    // Identify inputs by element count (robust to metadata ordering)
    const float* x = nullptr;
    const float* w_qkv = nullptr;
    const float* w_proj = nullptr;
    const float* b_proj = nullptr;
    const float* rel_bias = nullptr;
    for (int i = 0; i < n_in; i++) {
        switch (in_sizes[i]) {
            case 4194304: x = (const float*)d_in[i]; break;
            case 3145728: w_qkv = (const float*)d_in[i]; break;
            case 1048576: w_proj = (const float*)d_in[i]; break;
            case 1024:    b_proj = (const float*)d_in[i]; break;
            case 4112:    rel_bias = (const float*)d_in[i]; break;
            default: break;
        }
    }
    float* out = (float*)d_out;

    // Resolve DEVICE address of g_att (host shadow trap on ATS systems).
    float* att_dev = nullptr;
    cudaGetSymbolAddress((void**)&att_dev, g_att);

    const int M = B_ * T_;  // 4096

    const int smem1 = 2 * (2 * 1 * 8 * LDSM) * 8;  // SPLIT=1 double-buffered

    // 1) QKV projection, plain tf32 tensor cores, scatter epilogue
    {
        cudaFuncSetAttribute(gemm_tf32<1, 1>,
                             cudaFuncAttributeMaxDynamicSharedMemorySize, smem1);
        dim3 grid((3 * C_) / 128, M / 128);
        gemm_tf32<1, 1><<<grid, 256, smem1>>>(x, w_qkv, nullptr, nullptr,
                                              3 * C_, C_);
    }

    // 2) Local causal attention, tf32 tensor cores
    {
        cudaFuncSetAttribute(attn_tc,
                             cudaFuncAttributeMaxDynamicSharedMemorySize,
                             ATT_SMEM_BYTES);
        dim3 grid(T_ / 128, B_ * H_);
        attn_tc<<<grid, 256, ATT_SMEM_BYTES>>>(rel_bias);
    }

    // 3) Output projection + bias, plain tf32
    {
        cudaFuncSetAttribute(gemm_tf32<0, 1>,
                             cudaFuncAttributeMaxDynamicSharedMemorySize, smem1);
        dim3 grid(C_ / 128, M / 128);
        gemm_tf32<0, 1><<<grid, 256, smem1>>>(att_dev, w_proj, b_proj, out,
                                              C_, C_);
    }
}

// round 13
// speedup vs baseline: 2.2635x; 1.0603x over previous
#include <cuda_runtime.h>
#include <cstdint>

// Problem constants
#define B_ 2
#define T_ 2048
#define C_ 1024
#define H_ 16
#define HD_ 64
#define WIN_ 512
#define MAXREL_ 128
#define NBIAS_ 257

// Scratch (device globals; no allocation allowed)
__device__ float g_q[(size_t)B_ * H_ * T_ * HD_];
__device__ float g_k[(size_t)B_ * H_ * T_ * HD_];
__device__ float g_v[(size_t)B_ * H_ * T_ * HD_];
__device__ float g_att[(size_t)B_ * T_ * C_];

// ---------------------------------------------------------------------------
// tf32 helpers
// ---------------------------------------------------------------------------
__device__ __forceinline__ uint32_t f2tf(float a) {
    uint32_t r;
    asm("cvt.rna.tf32.f32 %0, %1;" : "=r"(r) : "f"(a));
    return r;
}

__device__ __forceinline__ void mma_tf32(float c[4], const uint32_t a[4],
                                         const uint32_t b[2]) {
    asm("mma.sync.aligned.m16n8k8.row.col.f32.tf32.tf32.f32 "
        "{%0,%1,%2,%3}, {%4,%5,%6,%7}, {%8,%9}, {%0,%1,%2,%3};"
        : "+f"(c[0]), "+f"(c[1]), "+f"(c[2]), "+f"(c[3])
        : "r"(a[0]), "r"(a[1]), "r"(a[2]), "r"(a[3]), "r"(b[0]), "r"(b[1]));
}

// ---------------------------------------------------------------------------
// TF32 tensor-core GEMM NT: C[m][n] = sum_k A[m][k] * B[n][k]
// CTA tile 256x128, BK=16, 256 threads (8 warps, 4x2), warp tile 64x64.
// Fragment-packed smem: uint2 holds (k, k+4); one LDS.64 per fragment.
// MODE 0: C = acc + bias[n].  MODE 1: QKV scatter epilogue.
// ---------------------------------------------------------------------------
#define ASTR 264   // uint2 row stride for A (256 + 8 pad)
#define BSTR 136   // uint2 row stride for B (128 + 8 pad)
#define SRC_A (8 * ASTR)            // 2112 uint2
#define SRC_B (8 * BSTR)            // 1088 uint2
#define SRC_AB (SRC_A + SRC_B)      // 3200 uint2 per buffer
#define GSMEM_BYTES (2 * SRC_AB * 8)  // 51200 B

__device__ __forceinline__ void store_row(uint2* plane, int stride, int row,
                                          int gs, int gu, float4 v) {
    const float* f = &v.x;
#pragma unroll
    for (int e = 0; e < 4; e++) {
        ((uint32_t*)&plane[(gs * 4 + e) * stride + row])[gu] = f2tf(f[e]);
    }
}

template <int MODE>
__global__ __launch_bounds__(256, 1)
void gemm_tf32(const float* __restrict__ A, const float* __restrict__ Bm,
               const float* __restrict__ bias, float* __restrict__ Cout,
               int N, int K) {
    extern __shared__ uint2 smem[];

    const int tid = threadIdx.x;
    const int warp = tid >> 5, lane = tid & 31;
    const int wm = warp & 3, wn = warp >> 2;     // 4 x 2 warp grid
    const int gid = lane >> 2, tig = lane & 3;
    const int bm = blockIdx.y * 256, bn = blockIdx.x * 128;

    const int r0 = tid >> 2;        // 0..63
    const int gt = tid & 3;
    const int gs = gt >> 1, gu = gt & 1;

    const float* Ag = A + (size_t)(bm + r0) * K + gt * 4;
    const float* Bg = Bm + (size_t)(bn + r0) * K + gt * 4;

    float acc[4][8][4];
#pragma unroll
    for (int i = 0; i < 4; i++)
#pragma unroll
        for (int j = 0; j < 8; j++)
#pragma unroll
            for (int e = 0; e < 4; e++) acc[i][j][e] = 0.f;

    const int NT = K >> 4;

    float4 ra[4], rb[2];
#pragma unroll
    for (int it = 0; it < 4; it++) ra[it] = *(const float4*)(Ag + (size_t)(it * 64) * K);
#pragma unroll
    for (int it = 0; it < 2; it++) rb[it] = *(const float4*)(Bg + (size_t)(it * 64) * K);
    {
        uint2* Ab = smem;
        uint2* Bb = smem + SRC_A;
#pragma unroll
        for (int it = 0; it < 4; it++) store_row(Ab, ASTR, r0 + it * 64, gs, gu, ra[it]);
#pragma unroll
        for (int it = 0; it < 2; it++) store_row(Bb, BSTR, r0 + it * 64, gs, gu, rb[it]);
    }
    __syncthreads();

    int buf = 0;
    for (int kt = 0; kt < NT; kt++) {
        if (kt + 1 < NT) {
            int off = (kt + 1) * 16;
#pragma unroll
            for (int it = 0; it < 4; it++)
                ra[it] = *(const float4*)(Ag + (size_t)(it * 64) * K + off);
#pragma unroll
            for (int it = 0; it < 2; it++)
                rb[it] = *(const float4*)(Bg + (size_t)(it * 64) * K + off);
        }
        const uint2* Ab = smem + buf * SRC_AB;
        const uint2* Bb = Ab + SRC_A;
#pragma unroll
        for (int s = 0; s < 2; s++) {
            uint32_t ah[4][4];
#pragma unroll
            for (int i = 0; i < 4; i++) {
                int m0 = wm * 64 + i * 16 + gid;
                uint2 lo = Ab[(s * 4 + tig) * ASTR + m0];
                uint2 hi = Ab[(s * 4 + tig) * ASTR + m0 + 8];
                ah[i][0] = lo.x; ah[i][1] = hi.x;
                ah[i][2] = lo.y; ah[i][3] = hi.y;
            }
#pragma unroll
            for (int j = 0; j < 8; j++) {
                int n0 = wn * 64 + j * 8 + gid;
                uint2 bv = Bb[(s * 4 + tig) * BSTR + n0];
                uint32_t bh[2] = {bv.x, bv.y};
#pragma unroll
                for (int i = 0; i < 4; i++) mma_tf32(acc[i][j], ah[i], bh);
            }
        }
        if (kt + 1 < NT) {
            uint2* An = smem + (buf ^ 1) * SRC_AB;
            uint2* Bn = An + SRC_A;
#pragma unroll
            for (int it = 0; it < 4; it++) store_row(An, ASTR, r0 + it * 64, gs, gu, ra[it]);
#pragma unroll
            for (int it = 0; it < 2; it++) store_row(Bn, BSTR, r0 + it * 64, gs, gu, rb[it]);
        }
        __syncthreads();
        buf ^= 1;
    }

    // Epilogue
#pragma unroll
    for (int i = 0; i < 4; i++) {
#pragma unroll
        for (int j = 0; j < 8; j++) {
            int nb = bn + wn * 64 + j * 8 + tig * 2;
            int m1 = bm + wm * 64 + i * 16 + gid;
            if (MODE == 0) {
                float2 bb = *(const float2*)(bias + nb);
                float2 v0, v1;
                v0.x = acc[i][j][0] + bb.x; v0.y = acc[i][j][1] + bb.y;
                v1.x = acc[i][j][2] + bb.x; v1.y = acc[i][j][3] + bb.y;
                *(float2*)(Cout + (size_t)m1 * N + nb) = v0;
                *(float2*)(Cout + (size_t)(m1 + 8) * N + nb) = v1;
            } else {
                int s = nb >> 10;
                int h = (nb >> 6) & 15;
                int d = nb & 63;
                float* base = (s == 0) ? g_q : (s == 1) ? g_k : g_v;
                int b = m1 >> 11, t = m1 & (T_ - 1);
                int b2 = (m1 + 8) >> 11, t2 = (m1 + 8) & (T_ - 1);
                float* dst = base + (((size_t)(b * H_ + h)) * T_ + t) * HD_ + d;
                float* dst2 = base + (((size_t)(b2 * H_ + h)) * T_ + t2) * HD_ + d;
                float2 v0, v1;
                v0.x = acc[i][j][0]; v0.y = acc[i][j][1];
                v1.x = acc[i][j][2]; v1.y = acc[i][j][3];
                *(float2*)dst = v0;
                *(float2*)dst2 = v1;
            }
        }
    }
}

// ---------------------------------------------------------------------------
// Tensor-core (tf32 mma.sync) flash attention — unchanged from R9 (passing).
// ---------------------------------------------------------------------------
#define QS32 66
#define KS32 66
#define VS32 132
#define PS32 66

#define OFF_Q 0
#define OFF_K (OFF_Q + 128 * 33)
#define OFF_V (OFF_K + 64 * 33)
#define OFF_P (OFF_V + 32 * 66)
#define OFF_BIAS (OFF_P + 128 * 33)
#define ATT_SMEM_U2 (OFF_BIAS + 130)
#define ATT_SMEM_BYTES (ATT_SMEM_U2 * 8)

__global__ __launch_bounds__(256, 2)
void attn_tc(const float* __restrict__ rel_bias) {
    extern __shared__ uint2 su[];
    uint32_t* Qs = (uint32_t*)(su + OFF_Q);
    uint32_t* Ks = (uint32_t*)(su + OFF_K);
    uint32_t* Vs = (uint32_t*)(su + OFF_V);
    uint32_t* Ps = (uint32_t*)(su + OFF_P);
    float* sb = (float*)(su + OFF_BIAS);

    const int tid = threadIdx.x;
    const int warp = tid >> 5, lane = tid & 31;
    const int g = lane >> 2, tig = lane & 3;
    const int bh = blockIdx.y;
    const int b = bh >> 4, h = bh & 15;
    const int q0 = blockIdx.x * 128;

    const float* qg = g_q + (size_t)bh * T_ * HD_;
    const float* kg = g_k + (size_t)bh * T_ * HD_;
    const float* vg = g_v + (size_t)bh * T_ * HD_;

    for (int r = tid; r < NBIAS_; r += 256) sb[r] = rel_bias[r * H_ + h];

#pragma unroll
    for (int it = 0; it < 8; it++) {
        int fi = tid + it * 256;
        int row = fi >> 4;
        int d0 = (fi & 15) << 2;
        float4 v = *(const float4*)(qg + (size_t)(q0 + row) * HD_ + d0);
#pragma unroll
        for (int e = 0; e < 4; e++) {
            int d = d0 + e, s_ = d >> 3, c = d & 7;
            Qs[row * QS32 + (s_ * 4 + (c & 3)) * 2 + (c >> 2)] =
                f2tf(((const float*)&v)[e]);
        }
    }
    __syncthreads();

    const int rg = warp * 16 + g;

    float oreg[8][4];
    float mrow[2], lrow[2];
#pragma unroll
    for (int nt = 0; nt < 8; nt++)
#pragma unroll
        for (int e = 0; e < 4; e++) oreg[nt][e] = 0.f;
    mrow[0] = mrow[1] = -1e30f;
    lrow[0] = lrow[1] = 0.f;

    int kt_lo = q0 - WIN_;
    if (kt_lo < 0) kt_lo = 0;
    const int kt_hi = q0 + 64;

    for (int kt = kt_lo; kt <= kt_hi; kt += 64) {
        __syncthreads();
#pragma unroll
        for (int it = 0; it < 4; it++) {
            int fi = tid + it * 256;
            int row = fi >> 4;
            int d0 = (fi & 15) << 2;
            float4 kv = *(const float4*)(kg + (size_t)(kt + row) * HD_ + d0);
            float4 vv = *(const float4*)(vg + (size_t)(kt + row) * HD_ + d0);
            int sk = row >> 3, ck = row & 7;
            int vbase = (sk * 4 + (ck & 3)) * VS32 + (ck >> 2);
#pragma unroll
            for (int e = 0; e < 4; e++) {
                int d = d0 + e, s_ = d >> 3, c = d & 7;
                Ks[row * KS32 + (s_ * 4 + (c & 3)) * 2 + (c >> 2)] =
                    f2tf(((const float*)&kv)[e]);
                Vs[vbase + d * 2] = f2tf(((const float*)&vv)[e]);
            }
        }
        __syncthreads();

        float sreg[8][4];
#pragma unroll
        for (int j = 0; j < 8; j++)
#pragma unroll
            for (int e = 0; e < 4; e++) sreg[j][e] = 0.f;
#pragma unroll
        for (int s_ = 0; s_ < 8; s_++) {
            uint2 qa0 = *(const uint2*)&Qs[rg * QS32 + (s_ * 4 + tig) * 2];
            uint2 qa1 = *(const uint2*)&Qs[(rg + 8) * QS32 + (s_ * 4 + tig) * 2];
            uint32_t a[4] = {qa0.x, qa1.x, qa0.y, qa1.y};
#pragma unroll
            for (int j = 0; j < 8; j++) {
                uint2 kb = *(const uint2*)&Ks[(8 * j + g) * KS32 + (s_ * 4 + tig) * 2];
                uint32_t bb[2] = {kb.x, kb.y};
                mma_tf32(sreg[j], a, bb);
            }
        }

#pragma unroll
        for (int hi = 0; hi < 2; hi++) {
            int gi = q0 + rg + 8 * hi;
            float mx = -1e30f;
#pragma unroll
            for (int j = 0; j < 8; j++)
#pragma unroll
                for (int e = 0; e < 2; e++) {
                    int key = kt + 8 * j + 2 * tig + e;
                    int dd = gi - key;
                    float val;
                    if (dd >= 0 && dd <= WIN_) {
                        int r = (dd > MAXREL_) ? (2 * MAXREL_) : (dd + MAXREL_);
                        val = sreg[j][2 * hi + e] * 0.125f + sb[r];
                    } else {
                        val = -1e30f;
                    }
                    sreg[j][2 * hi + e] = val;
                    mx = fmaxf(mx, val);
                }
            mx = fmaxf(mx, __shfl_xor_sync(0xffffffffu, mx, 1));
            mx = fmaxf(mx, __shfl_xor_sync(0xffffffffu, mx, 2));
            float mn = fmaxf(mrow[hi], mx);
            float alpha = __expf(mrow[hi] - mn);
            mrow[hi] = mn;
            float ps = 0.f;
#pragma unroll
            for (int j = 0; j < 8; j++)
#pragma unroll
                for (int e = 0; e < 2; e++) {
                    float v = sreg[j][2 * hi + e];
                    float p = (v > -1e29f) ? __expf(v - mn) : 0.f;
                    sreg[j][2 * hi + e] = p;
                    ps += p;
                }
            ps += __shfl_xor_sync(0xffffffffu, ps, 1);
            ps += __shfl_xor_sync(0xffffffffu, ps, 2);
            lrow[hi] = lrow[hi] * alpha + ps;
#pragma unroll
            for (int nt = 0; nt < 8; nt++) {
                oreg[nt][2 * hi] *= alpha;
                oreg[nt][2 * hi + 1] *= alpha;
            }
        }

#pragma unroll
        for (int j = 0; j < 8; j++)
#pragma unroll
            for (int hi = 0; hi < 2; hi++)
#pragma unroll
                for (int e = 0; e < 2; e++) {
                    int c = 2 * tig + e;
                    Ps[(rg + 8 * hi) * PS32 + (j * 4 + (c & 3)) * 2 + (c >> 2)] =
                        f2tf(sreg[j][2 * hi + e]);
                }
        __syncthreads();

#pragma unroll
        for (int s_ = 0; s_ < 8; s_++) {
            uint2 pa0 = *(const uint2*)&Ps[rg * PS32 + (s_ * 4 + tig) * 2];
            uint2 pa1 = *(const uint2*)&Ps[(rg + 8) * PS32 + (s_ * 4 + tig) * 2];
            uint32_t a[4] = {pa0.x, pa1.x, pa0.y, pa1.y};
#pragma unroll
            for (int nt = 0; nt < 8; nt++) {
                uint2 vb = *(const uint2*)&Vs[(s_ * 4 + tig) * VS32 + (g + 8 * nt) * 2];
                uint32_t bb[2] = {vb.x, vb.y};
                mma_tf32(oreg[nt], a, bb);
            }
        }
    }

#pragma unroll
    for (int hi = 0; hi < 2; hi++) {
        float inv = 1.f / lrow[hi];
        int gi = q0 + rg + 8 * hi;
        float* dst = g_att + ((size_t)(b * T_ + gi)) * C_ + h * HD_;
#pragma unroll
        for (int nt = 0; nt < 8; nt++) {
            float2 v;
            v.x = oreg[nt][2 * hi] * inv;
            v.y = oreg[nt][2 * hi + 1] * inv;
            *(float2*)(dst + 8 * nt + 2 * tig) = v;
        }
    }
}

// ---------------------------------------------------------------------------
extern "C" void kernel_launch(void* const* d_in, const int* in_sizes, int n_in,
                              void* d_out, int out_size) {
    const float* x = nullptr;
    const float* w_qkv = nullptr;
    const float* w_proj = nullptr;
    const float* b_proj = nullptr;
    const float* rel_bias = nullptr;
    for (int i = 0; i < n_in; i++) {
        switch (in_sizes[i]) {
            case 4194304: x = (const float*)d_in[i]; break;
            case 3145728: w_qkv = (const float*)d_in[i]; break;
            case 1048576: w_proj = (const float*)d_in[i]; break;
            case 1024:    b_proj = (const float*)d_in[i]; break;
            case 4112:    rel_bias = (const float*)d_in[i]; break;
            default: break;
        }
    }
    float* out = (float*)d_out;

    // Resolve DEVICE address of g_att (host shadow trap on ATS systems).
    float* att_dev = nullptr;
    cudaGetSymbolAddress((void**)&att_dev, g_att);

    const int M = B_ * T_;  // 4096

    // 1) QKV projection, tf32 tensor cores (64x64 warp tiles), scatter epilogue
    {
        cudaFuncSetAttribute(gemm_tf32<1>,
                             cudaFuncAttributeMaxDynamicSharedMemorySize,
                             GSMEM_BYTES);
        dim3 grid((3 * C_) / 128, M / 256);
        gemm_tf32<1><<<grid, 256, GSMEM_BYTES>>>(x, w_qkv, nullptr, nullptr,
                                                 3 * C_, C_);
    }

    // 2) Local causal attention, tf32 mma.sync
    {
        cudaFuncSetAttribute(attn_tc,
                             cudaFuncAttributeMaxDynamicSharedMemorySize,
                             ATT_SMEM_BYTES);
        dim3 grid(T_ / 128, B_ * H_);
        attn_tc<<<grid, 256, ATT_SMEM_BYTES>>>(rel_bias);
    }

    // 3) Output projection + bias, tf32 tensor cores
    {
        cudaFuncSetAttribute(gemm_tf32<0>,
                             cudaFuncAttributeMaxDynamicSharedMemorySize,
                             GSMEM_BYTES);
        dim3 grid(C_ / 128, M / 256);
        gemm_tf32<0><<<grid, 256, GSMEM_BYTES>>>(att_dev, w_proj, b_proj, out,
                                                 C_, C_);
    }
}